// round 5
// baseline (speedup 1.0000x reference)
#include <cuda_runtime.h>

// VIN_68401649156499 — round 5: y-interleaved pair planes + FFMA2, 512 threads
// (4 warps/SMSP for latency hiding; per-SM FFMA2 floor unchanged at 1440 cyc/iter)
//
// Pair = (v[y][x], v[y+32][x]) stored contiguously -> all conv operands are aligned
// LDS.64, zero repack MOVs. 512 thr: lane l = pair-row, warp w owns pair-cols 4w..4w+3.

#define PS 67                 // pair stride per interleaved row (odd -> conflict-free)
#define PROWS 34              // pair rows j=0..33 (logical -1..32)
#define PPLANE (PS * PROWS)   // 2278 pairs
#define FRS 68                // flat scratch row stride (floats)
#define NPIX 4096
typedef unsigned long long ull;

__device__ __forceinline__ ull pk(float lo, float hi) {
    ull r; asm("mov.b64 %0, {%1, %2};" : "=l"(r) : "f"(lo), "f"(hi)); return r;
}
__device__ __forceinline__ float2 up(ull v) {
    float2 r; asm("mov.b64 {%0, %1}, %2;" : "=f"(r.x), "=f"(r.y) : "l"(v)); return r;
}
__device__ __forceinline__ ull ffma2(ull a, ull b, ull c) {
    ull d; asm("fma.rn.f32x2 %0, %1, %2, %3;" : "=l"(d) : "l"(a), "l"(b), "l"(c)); return d;
}

// shared: P0 [0..2277], P1 [2278..4555], ww pairs [4556..4600], weff floats after
__shared__ ull s_mem8[4612];

// acc[a][c] = qr[a][c] + conv3x3(w_w[a], v)  over this thread's 4 pair-columns
__device__ __forceinline__ void bellman(ull acc[5][4], const ull* __restrict__ vi,
                                        const ull qrp[5][4], int l, int x0) {
    const ull* s_ww = s_mem8 + 4556;
    #pragma unroll
    for (int dy = 0; dy < 3; ++dy) {
        const ull* row = vi + (l + dy) * PS + x0;   // row[k] = pair col x0-1+k
        ull L[6];
        #pragma unroll
        for (int k = 0; k < 6; ++k) L[k] = row[k];
        #pragma unroll
        for (int a = 0; a < 5; ++a) {
            ull w0 = s_ww[a * 9 + dy * 3 + 0];
            ull w1 = s_ww[a * 9 + dy * 3 + 1];
            ull w2 = s_ww[a * 9 + dy * 3 + 2];
            #pragma unroll
            for (int c = 0; c < 4; ++c) {
                ull t = (dy == 0) ? ffma2(w0, L[c], qrp[a][c])   // fused acc init
                                  : ffma2(w0, L[c], acc[a][c]);
                t = ffma2(w1, L[c + 1], t);
                acc[a][c] = ffma2(w2, L[c + 2], t);
            }
        }
    }
}

__global__ __launch_bounds__(512, 1) void vin_kernel(
    const float* __restrict__ input,   // [128,2,64,64]
    const int*   __restrict__ coords,  // [128,4]
    const float* __restrict__ w_h,     // [150,2,3,3]
    const float* __restrict__ b_h,     // [150]
    const float* __restrict__ w_r,     // [150]
    const float* __restrict__ w_q,     // [5,1,3,3]
    const float* __restrict__ w_w,     // [5,1,3,3]
    float* __restrict__ out_q,         // [128,5,64,64]
    float* __restrict__ out_logits)    // [128,5]
{
    const int b  = blockIdx.x;
    const int t  = threadIdx.x;
    const int l  = t & 31;            // pair row (pixel rows l and l+32)
    const int x0 = (t >> 5) * 4;      // pair cols x0..x0+3

    float* fmem  = (float*)s_mem8;     // flat view (9112 floats over P0+P1)
    float* flatA = fmem;               // setup scratch A
    float* flatB = fmem + 2 * PPLANE;  // setup scratch B
    float* sweff = (float*)(s_mem8 + 4601);

    // ---- zero plane region; build weff/beff; pack iteration weights ----
    for (int k = t; k < 2 * PPLANE * 2; k += 512) fmem[k] = 0.f;
    if (t < 18) {
        float s = 0.f;
        for (int c = 0; c < 150; ++c) s += w_r[c] * w_h[c * 18 + t];
        sweff[t] = s;
    } else if (t == 18) {
        float s = 0.f;
        for (int c = 0; c < 150; ++c) s += w_r[c] * b_h[c];
        sweff[18] = s;
    } else if (t >= 32 && t < 77) {
        float w = w_w[t - 32];
        s_mem8[4556 + t - 32] = pk(w, w);
    }
    __syncthreads();

    // ---- stage input channels into flat scratch (pixel (y,x) at (y+1)*FRS+x+1) ----
    const float* inb = input + (size_t)b * 2 * NPIX;
    #pragma unroll
    for (int k = 0; k < 16; ++k) {
        int lin = k * 512 + t;
        int rem = lin & 4095;
        float* dst = (lin < 4096) ? flatA : flatB;
        dst[((rem >> 6) + 1) * FRS + (rem & 63) + 1] = inb[lin];
    }
    __syncthreads();

    // ---- r = conv(input, weff) + beff at this thread's 8 pixels ----
    float weff[18];
    #pragma unroll
    for (int k = 0; k < 18; ++k) weff[k] = sweff[k];
    const float beff = sweff[18];

    float rA[4], rB[4];
    #pragma unroll
    for (int c = 0; c < 4; ++c) {
        float sA = beff, sB = beff;
        #pragma unroll
        for (int dy = 0; dy < 3; ++dy)
            #pragma unroll
            for (int dx = 0; dx < 3; ++dx) {
                int oA = (l + dy) * FRS + x0 + c + dx;
                int oB = (l + 32 + dy) * FRS + x0 + c + dx;
                float w0 = weff[dy * 3 + dx], w1 = weff[9 + dy * 3 + dx];
                sA = fmaf(w0, flatA[oA], sA); sA = fmaf(w1, flatB[oA], sA);
                sB = fmaf(w0, flatA[oB], sB); sB = fmaf(w1, flatB[oB], sB);
            }
        rA[c] = sA; rB[c] = sB;
    }
    __syncthreads();

    // ---- r -> flatA ----
    #pragma unroll
    for (int c = 0; c < 4; ++c) {
        flatA[(l + 1) * FRS + x0 + c + 1]  = rA[c];
        flatA[(l + 33) * FRS + x0 + c + 1] = rB[c];
    }
    __syncthreads();

    // ---- qr = conv(r, w_q) -> packed register pairs; v0 = max_a ----
    float wq[45];
    #pragma unroll
    for (int k = 0; k < 45; ++k) wq[k] = w_q[k];

    ull  qrp[5][4];
    float v0A[4], v0B[4];
    #pragma unroll
    for (int c = 0; c < 4; ++c) {
        float qA[5], qB[5];
        #pragma unroll
        for (int a = 0; a < 5; ++a) { qA[a] = 0.f; qB[a] = 0.f; }
        #pragma unroll
        for (int dy = 0; dy < 3; ++dy)
            #pragma unroll
            for (int dx = 0; dx < 3; ++dx) {
                float fa = flatA[(l + dy) * FRS + x0 + c + dx];
                float fb = flatA[(l + 32 + dy) * FRS + x0 + c + dx];
                #pragma unroll
                for (int a = 0; a < 5; ++a) {
                    qA[a] = fmaf(wq[a * 9 + dy * 3 + dx], fa, qA[a]);
                    qB[a] = fmaf(wq[a * 9 + dy * 3 + dx], fb, qB[a]);
                }
            }
        float mA = qA[0], mB = qB[0];
        #pragma unroll
        for (int a = 1; a < 5; ++a) { mA = fmaxf(mA, qA[a]); mB = fmaxf(mB, qB[a]); }
        v0A[c] = mA; v0B[c] = mB;
        #pragma unroll
        for (int a = 0; a < 5; ++a) qrp[a][c] = pk(qA[a], qB[a]);
    }
    __syncthreads();

    // ---- re-zero planes (scratch is garbage), write v0 + halos into P1 ----
    for (int k = t; k < 2 * PPLANE * 2; k += 512) fmem[k] = 0.f;
    __syncthreads();

    ull* P0 = s_mem8;
    ull* P1 = s_mem8 + PPLANE;
    #pragma unroll
    for (int c = 0; c < 4; ++c)
        P1[(l + 1) * PS + x0 + c + 1] = pk(v0A[c], v0B[c]);
    if (l == 31) {
        #pragma unroll
        for (int c = 0; c < 4; ++c) P1[x0 + c + 1] = pk(0.f, v0A[c]);           // j=0: (0, v[31])
    }
    if (l == 0) {
        #pragma unroll
        for (int c = 0; c < 4; ++c) P1[33 * PS + x0 + c + 1] = pk(v0B[c], 0.f); // j=33: (v[32], 0)
    }
    __syncthreads();

    // ---- 79 Bellman iterations (even it: P1 -> P0) ----
    for (int it = 0; it < 79; ++it) {
        const ull* vi = (it & 1) ? P0 : P1;
        ull*       vo = (it & 1) ? P1 : P0;
        ull acc[5][4];
        bellman(acc, vi, qrp, l, x0);

        float mA[4], mB[4];
        #pragma unroll
        for (int c = 0; c < 4; ++c) {
            float2 m = up(acc[0][c]);
            #pragma unroll
            for (int a = 1; a < 5; ++a) {
                float2 q = up(acc[a][c]);
                m.x = fmaxf(m.x, q.x);
                m.y = fmaxf(m.y, q.y);
            }
            mA[c] = m.x; mB[c] = m.y;
            vo[(l + 1) * PS + x0 + c + 1] = pk(m.x, m.y);
        }
        if (l == 31) {
            #pragma unroll
            for (int c = 0; c < 4; ++c) vo[x0 + c + 1] = pk(0.f, mA[c]);
        }
        if (l == 0) {
            #pragma unroll
            for (int c = 0; c < 4; ++c) vo[33 * PS + x0 + c + 1] = pk(mB[c], 0.f);
        }
        __syncthreads();
    }

    // ---- final q from P0 ----
    ull acc[5][4];
    bellman(acc, P0, qrp, l, x0);

    const int sx = coords[b * 4 + 0];
    const int sy = coords[b * 4 + 1];
    float* oq = out_q + (size_t)b * 5 * NPIX;

    #pragma unroll
    for (int a = 0; a < 5; ++a) {
        float2 f[4];
        #pragma unroll
        for (int c = 0; c < 4; ++c) f[c] = up(acc[a][c]);
        float* baseA = oq + a * NPIX + l * 64 + x0;
        float* baseB = oq + a * NPIX + (l + 32) * 64 + x0;
        *reinterpret_cast<float4*>(baseA) = make_float4(f[0].x, f[1].x, f[2].x, f[3].x);
        *reinterpret_cast<float4*>(baseB) = make_float4(f[0].y, f[1].y, f[2].y, f[3].y);
        if (sy >= x0 && sy < x0 + 4) {
            if (sx == l)      out_logits[b * 5 + a] = f[sy - x0].x;
            if (sx == l + 32) out_logits[b * 5 + a] = f[sy - x0].y;
        }
    }
}

extern "C" void kernel_launch(void* const* d_in, const int* in_sizes, int n_in,
                              void* d_out, int out_size) {
    const float* input  = (const float*)d_in[0];
    const int*   coords = (const int*)  d_in[1];
    const float* w_h    = (const float*)d_in[2];
    const float* b_h    = (const float*)d_in[3];
    const float* w_r    = (const float*)d_in[4];
    const float* w_q    = (const float*)d_in[5];
    const float* w_w    = (const float*)d_in[6];
    float* out = (float*)d_out;

    vin_kernel<<<128, 512>>>(input, coords, w_h, b_h, w_r, w_q, w_w,
                             out, out + 128 * 5 * NPIX);
}

// round 6
// speedup vs baseline: 1.0040x; 1.0040x over previous
#include <cuda_runtime.h>

// VIN_68401649156499 — round 6: R1 scalar floor kernel + exact-fixpoint early break.
//
// r = conv(input, w_eff) + b_eff   (w_eff collapses the 150-ch hidden layer; in-kernel)
// qr_a = conv(r, w_q[a])           (registers, loop invariant)
// v0 = max_a qr_a
// up to 79x: v = max_a (qr_a + conv(v, w_w[a]))  in SMEM double-buffer.
//   The map is an fp32 contraction -> v hits an EXACT bitwise fixpoint; once
//   v_{t+1}==v_t for every pixel, all later iterates are bit-identical, so the
//   CTA breaks with output identical to the full 80-iteration run.
// final q_a = qr_a + conv(v, w_w[a]); logits = q[b,:,sx,sy]

#define BH 66           // 64 + 2 halo
#define NPIX 4096

__global__ __launch_bounds__(512, 1) void vin_kernel(
    const float* __restrict__ input,   // [128,2,64,64]
    const int*   __restrict__ coords,  // [128,4]
    const float* __restrict__ w_h,     // [150,2,3,3]
    const float* __restrict__ b_h,     // [150]
    const float* __restrict__ w_r,     // [150]
    const float* __restrict__ w_q,     // [5,1,3,3]
    const float* __restrict__ w_w,     // [5,1,3,3]
    float* __restrict__ out_q,         // [128,5,64,64]
    float* __restrict__ out_logits)    // [128,5]
{
    __shared__ float buf[2][BH * BH];
    __shared__ float sweff[20];
    __shared__ int   s_flag[2];

    const int b  = blockIdx.x;
    const int t  = threadIdx.x;
    const int y  = t >> 3;          // 0..63
    const int x0 = (t & 7) * 8;     // 0,8,...,56

    // ---- zero both padded planes (halo must stay zero forever) ----
    for (int k = t; k < 2 * BH * BH; k += 512) (&buf[0][0])[k] = 0.f;

    // ---- collapse hidden layer: weff[18], beff (same summation order as ref path) ----
    if (t < 18) {
        float s = 0.f;
        for (int c = 0; c < 150; ++c) s += w_r[c] * w_h[c * 18 + t];
        sweff[t] = s;
    } else if (t == 18) {
        float s = 0.f;
        for (int c = 0; c < 150; ++c) s += w_r[c] * b_h[c];
        sweff[18] = s;
    } else if (t == 19) {
        s_flag[0] = 0; s_flag[1] = 0;
    }
    __syncthreads();

    // ---- stage input (2 channels) into padded planes ----
    const float* inb = input + (size_t)b * 2 * NPIX;
    #pragma unroll
    for (int k = 0; k < 16; ++k) {
        int lin = k * 512 + t;              // 0..8191
        int li  = lin >> 12;
        int rem = lin & 4095;
        buf[li][((rem >> 6) + 1) * BH + (rem & 63) + 1] = inb[lin];
    }
    __syncthreads();

    // ---- r = conv(input, w_eff) + b_eff  (into registers) ----
    float weff[18];
    #pragma unroll
    for (int k = 0; k < 18; ++k) weff[k] = sweff[k];
    const float beff = sweff[18];

    float rloc[8];
    #pragma unroll
    for (int i = 0; i < 8; ++i) {
        float s = beff;
        #pragma unroll
        for (int li = 0; li < 2; ++li)
            #pragma unroll
            for (int dy = 0; dy < 3; ++dy)
                #pragma unroll
                for (int dx = 0; dx < 3; ++dx)
                    s = fmaf(weff[li * 9 + dy * 3 + dx],
                             buf[li][(y + dy) * BH + x0 + i + dx], s);
        rloc[i] = s;
    }
    __syncthreads();

    // ---- store r into buf[1] interior (halo already zero) ----
    #pragma unroll
    for (int i = 0; i < 8; ++i) buf[1][(y + 1) * BH + x0 + i + 1] = rloc[i];
    __syncthreads();

    // ---- qr_a = conv(r, w_q[a])  (registers, loop invariant) ----
    float wq[45];
    #pragma unroll
    for (int k = 0; k < 45; ++k) wq[k] = w_q[k];

    float qr[5][8];
    #pragma unroll
    for (int i = 0; i < 8; ++i) {
        #pragma unroll
        for (int a = 0; a < 5; ++a) {
            float s = 0.f;
            #pragma unroll
            for (int dy = 0; dy < 3; ++dy)
                #pragma unroll
                for (int dx = 0; dx < 3; ++dx)
                    s = fmaf(wq[a * 9 + dy * 3 + dx],
                             buf[1][(y + dy) * BH + x0 + i + dx], s);
            qr[a][i] = s;
        }
    }

    // ---- v0 = max_a qr_a  -> buf[0] ----
    #pragma unroll
    for (int i = 0; i < 8; ++i) {
        float v = qr[0][i];
        #pragma unroll
        for (int a = 1; a < 5; ++a) v = fmaxf(v, qr[a][i]);
        buf[0][(y + 1) * BH + x0 + i + 1] = v;
    }

    float ww[45];
    #pragma unroll
    for (int k = 0; k < 45; ++k) ww[k] = w_w[k];
    __syncthreads();

    // ---- up to 79 Bellman iterations, exact-fixpoint early break ----
    const float* vfin = buf[1];
    for (int it = 0; it < 79; ++it) {
        const float* vi = buf[it & 1];
        float*       vo = buf[1 - (it & 1)];
        if (t == 0) s_flag[(it + 1) & 1] = 0;   // reset next flag before this barrier
        bool changed = false;
        #pragma unroll
        for (int i = 0; i < 8; ++i) {
            float q0 = qr[0][i], q1 = qr[1][i], q2 = qr[2][i],
                  q3 = qr[3][i], q4 = qr[4][i];
            #pragma unroll
            for (int dy = 0; dy < 3; ++dy) {
                #pragma unroll
                for (int dx = 0; dx < 3; ++dx) {
                    float vv = vi[(y + dy) * BH + x0 + i + dx];
                    q0 = fmaf(ww[0 * 9 + dy * 3 + dx], vv, q0);
                    q1 = fmaf(ww[1 * 9 + dy * 3 + dx], vv, q1);
                    q2 = fmaf(ww[2 * 9 + dy * 3 + dx], vv, q2);
                    q3 = fmaf(ww[3 * 9 + dy * 3 + dx], vv, q3);
                    q4 = fmaf(ww[4 * 9 + dy * 3 + dx], vv, q4);
                }
            }
            float v = fmaxf(fmaxf(q0, q1), fmaxf(q2, fmaxf(q3, q4)));
            float oldc = vi[(y + 1) * BH + x0 + i + 1];   // CSEs with dy=1,dx=1 tap
            changed |= (v != oldc);
            vo[(y + 1) * BH + x0 + i + 1] = v;
        }
        if (changed) s_flag[it & 1] = 1;
        vfin = vo;
        __syncthreads();
        if (s_flag[it & 1] == 0) break;   // bitwise stationary: rest of loop is identity
    }

    // ---- final q from vfin ----
    const int sx = coords[b * 4 + 0];
    const int sy = coords[b * 4 + 1];
    float* oq = out_q + (size_t)b * 5 * NPIX;

    float qf[5][8];
    #pragma unroll
    for (int i = 0; i < 8; ++i) {
        float q0 = qr[0][i], q1 = qr[1][i], q2 = qr[2][i],
              q3 = qr[3][i], q4 = qr[4][i];
        #pragma unroll
        for (int dy = 0; dy < 3; ++dy) {
            #pragma unroll
            for (int dx = 0; dx < 3; ++dx) {
                float vv = vfin[(y + dy) * BH + x0 + i + dx];
                q0 = fmaf(ww[0 * 9 + dy * 3 + dx], vv, q0);
                q1 = fmaf(ww[1 * 9 + dy * 3 + dx], vv, q1);
                q2 = fmaf(ww[2 * 9 + dy * 3 + dx], vv, q2);
                q3 = fmaf(ww[3 * 9 + dy * 3 + dx], vv, q3);
                q4 = fmaf(ww[4 * 9 + dy * 3 + dx], vv, q4);
            }
        }
        qf[0][i] = q0; qf[1][i] = q1; qf[2][i] = q2; qf[3][i] = q3; qf[4][i] = q4;
        if (y == sx && (x0 + i) == sy) {
            out_logits[b * 5 + 0] = q0;
            out_logits[b * 5 + 1] = q1;
            out_logits[b * 5 + 2] = q2;
            out_logits[b * 5 + 3] = q3;
            out_logits[b * 5 + 4] = q4;
        }
    }

    // vectorized, coalesced q stores
    #pragma unroll
    for (int a = 0; a < 5; ++a) {
        float* base = oq + a * NPIX + y * 64 + x0;
        *reinterpret_cast<float4*>(base)     = make_float4(qf[a][0], qf[a][1], qf[a][2], qf[a][3]);
        *reinterpret_cast<float4*>(base + 4) = make_float4(qf[a][4], qf[a][5], qf[a][6], qf[a][7]);
    }
}

extern "C" void kernel_launch(void* const* d_in, const int* in_sizes, int n_in,
                              void* d_out, int out_size) {
    const float* input  = (const float*)d_in[0];
    const int*   coords = (const int*)  d_in[1];
    const float* w_h    = (const float*)d_in[2];
    const float* b_h    = (const float*)d_in[3];
    const float* w_r    = (const float*)d_in[4];
    const float* w_q    = (const float*)d_in[5];
    const float* w_w    = (const float*)d_in[6];
    float* out = (float*)d_out;

    vin_kernel<<<128, 512>>>(input, coords, w_h, b_h, w_r, w_q, w_w,
                             out, out + 128 * 5 * NPIX);
}

// round 7
// speedup vs baseline: 1.0366x; 1.0325x over previous
#include <cuda_runtime.h>

// VIN_68401649156499 — round 7: pair-interleaved FFMA2 loop, weights register-resident,
// qr streamed from SMEM (independent conflict-free loads that double as acc init).
//
// Pair = (v[y][x], v[y+32][x]) stored contiguously -> all conv operands are aligned
// LDS.64, zero repack MOVs. 256 thr: lane l = pair-row, warp w owns pair-cols 8w..8w+7.

#define PS 67                 // pair stride (ull) per interleaved row (odd -> conflict-free)
#define PROWS 34              // pair rows 0..33 (logical -1..32)
#define PPLANE (PS * PROWS)   // 2278 pairs
#define FRS 68                // flat scratch row stride (floats)
#define NPIX 4096
typedef unsigned long long ull;

__device__ __forceinline__ ull pk(float lo, float hi) {
    ull r; asm("mov.b64 %0, {%1, %2};" : "=l"(r) : "f"(lo), "f"(hi)); return r;
}
__device__ __forceinline__ float2 up(ull v) {
    float2 r; asm("mov.b64 {%0, %1}, %2;" : "=f"(r.x), "=f"(r.y) : "l"(v)); return r;
}
__device__ __forceinline__ ull ffma2(ull a, ull b, ull c) {
    ull d; asm("fma.rn.f32x2 %0, %1, %2, %3;" : "=l"(d) : "l"(a), "l"(b), "l"(c)); return d;
}

__shared__ float s_weff[20];
__shared__ ull   s_ww[45];

// acc[a][c] = qr[a][c] (from SMEM) + conv3x3(w_w[a], v) over this thread's 8 pair-cols
__device__ __forceinline__ void bellman(ull acc[5][8], const ull* __restrict__ vi,
                                        const ull* __restrict__ qrs, const ull ww[45],
                                        int l, int x0, int t) {
    #pragma unroll
    for (int a = 0; a < 5; ++a)
        #pragma unroll
        for (int c = 0; c < 8; ++c)
            acc[a][c] = qrs[(a * 8 + c) * 256 + t];   // 40 independent LDS.64, 2wf each

    #pragma unroll
    for (int dy = 0; dy < 3; ++dy) {
        const ull* row = vi + (l + dy) * PS + x0;     // row[k] = pair col x0-1+k
        ull L[10];
        #pragma unroll
        for (int k = 0; k < 10; ++k) L[k] = row[k];
        #pragma unroll
        for (int a = 0; a < 5; ++a) {
            ull w0 = ww[a * 9 + dy * 3 + 0];
            ull w1 = ww[a * 9 + dy * 3 + 1];
            ull w2 = ww[a * 9 + dy * 3 + 2];
            #pragma unroll
            for (int c = 0; c < 8; ++c) {
                ull s = ffma2(w0, L[c], acc[a][c]);
                s = ffma2(w1, L[c + 1], s);
                acc[a][c] = ffma2(w2, L[c + 2], s);
            }
        }
    }
}

__global__ __launch_bounds__(256, 1) void vin_kernel(
    const float* __restrict__ input,   // [128,2,64,64]
    const int*   __restrict__ coords,  // [128,4]
    const float* __restrict__ w_h,     // [150,2,3,3]
    const float* __restrict__ b_h,     // [150]
    const float* __restrict__ w_r,     // [150]
    const float* __restrict__ w_q,     // [5,1,3,3]
    const float* __restrict__ w_w,     // [5,1,3,3]
    float* __restrict__ out_q,         // [128,5,64,64]
    float* __restrict__ out_logits)    // [128,5]
{
    extern __shared__ ull dsm[];
    ull*  P0   = dsm;                  // PPLANE
    ull*  P1   = dsm + PPLANE;         // PPLANE
    ull*  qrs  = dsm + 2 * PPLANE;     // 40*256 ull = 81920B; aliased as setup scratch
    float* flatA = (float*)qrs;                 // [66][68] floats
    float* flatB = (float*)qrs + FRS * 66;      // [66][68] floats

    const int b  = blockIdx.x;
    const int t  = threadIdx.x;
    const int l  = t & 31;             // pair row (pixel rows l and l+32)
    const int x0 = (t >> 5) * 8;       // pair cols x0..x0+7

    // ---- zero planes + scratch region (halos must stay zero) ----
    for (int k = t; k < 2 * PPLANE; k += 256) dsm[k] = 0ull;
    for (int k = t; k < 2 * FRS * 66; k += 256) ((float*)qrs)[k] = 0.f;

    // ---- collapse hidden layer; pack iteration weights into smem ----
    if (t < 18) {
        float s = 0.f;
        for (int c = 0; c < 150; ++c) s += w_r[c] * w_h[c * 18 + t];
        s_weff[t] = s;
    } else if (t == 18) {
        float s = 0.f;
        for (int c = 0; c < 150; ++c) s += w_r[c] * b_h[c];
        s_weff[18] = s;
    } else if (t >= 32 && t < 77) {
        float w = w_w[t - 32];
        s_ww[t - 32] = pk(w, w);
    }
    __syncthreads();

    // ---- stage input channels into flat scratch (pixel (y,x) at (y+1)*FRS+x+1) ----
    const float* inb = input + (size_t)b * 2 * NPIX;
    #pragma unroll
    for (int k = 0; k < 32; ++k) {
        int lin = k * 256 + t;
        int rem = lin & 4095;
        float* dst = (lin < 4096) ? flatA : flatB;
        dst[((rem >> 6) + 1) * FRS + (rem & 63) + 1] = inb[lin];
    }
    __syncthreads();

    // ---- r = conv(input, weff) + beff at this thread's 16 pixels ----
    float weff[18];
    #pragma unroll
    for (int k = 0; k < 18; ++k) weff[k] = s_weff[k];
    const float beff = s_weff[18];

    float rA[8], rB[8];
    #pragma unroll
    for (int c = 0; c < 8; ++c) {
        float sA = beff, sB = beff;
        #pragma unroll
        for (int dy = 0; dy < 3; ++dy)
            #pragma unroll
            for (int dx = 0; dx < 3; ++dx) {
                int oA = (l + dy) * FRS + x0 + c + dx;
                int oB = (l + 32 + dy) * FRS + x0 + c + dx;
                float w0 = weff[dy * 3 + dx], w1 = weff[9 + dy * 3 + dx];
                sA = fmaf(w0, flatA[oA], sA); sA = fmaf(w1, flatB[oA], sA);
                sB = fmaf(w0, flatA[oB], sB); sB = fmaf(w1, flatB[oB], sB);
            }
        rA[c] = sA; rB[c] = sB;
    }
    __syncthreads();

    // ---- r -> flatA (overwrite ch0 scratch; halo stays zero) ----
    #pragma unroll
    for (int c = 0; c < 8; ++c) {
        flatA[(l + 1) * FRS + x0 + c + 1]  = rA[c];
        flatA[(l + 33) * FRS + x0 + c + 1] = rB[c];
    }
    __syncthreads();

    // ---- qr = conv(r, w_q) -> register pairs; v0 = max_a -> P1 ----
    float wq[45];
    #pragma unroll
    for (int k = 0; k < 45; ++k) wq[k] = w_q[k];

    ull  qrp[5][8];
    float v0A[8], v0B[8];
    #pragma unroll
    for (int c = 0; c < 8; ++c) {
        float qA[5], qB[5];
        #pragma unroll
        for (int a = 0; a < 5; ++a) { qA[a] = 0.f; qB[a] = 0.f; }
        #pragma unroll
        for (int dy = 0; dy < 3; ++dy)
            #pragma unroll
            for (int dx = 0; dx < 3; ++dx) {
                float fa = flatA[(l + dy) * FRS + x0 + c + dx];
                float fb = flatA[(l + 32 + dy) * FRS + x0 + c + dx];
                #pragma unroll
                for (int a = 0; a < 5; ++a) {
                    qA[a] = fmaf(wq[a * 9 + dy * 3 + dx], fa, qA[a]);
                    qB[a] = fmaf(wq[a * 9 + dy * 3 + dx], fb, qB[a]);
                }
            }
        float mA = qA[0], mB = qB[0];
        #pragma unroll
        for (int a = 1; a < 5; ++a) { mA = fmaxf(mA, qA[a]); mB = fmaxf(mB, qB[a]); }
        v0A[c] = mA; v0B[c] = mB;
        #pragma unroll
        for (int a = 0; a < 5; ++a) qrp[a][c] = pk(qA[a], qB[a]);
    }
    __syncthreads();   // all reads of flatA done before qrs overwrites the region

    // ---- qrp -> qrs [(a,c)][t]; v0 + halo pair-rows -> P1 ----
    #pragma unroll
    for (int a = 0; a < 5; ++a)
        #pragma unroll
        for (int c = 0; c < 8; ++c)
            qrs[(a * 8 + c) * 256 + t] = qrp[a][c];

    #pragma unroll
    for (int c = 0; c < 8; ++c)
        P1[(l + 1) * PS + x0 + c + 1] = pk(v0A[c], v0B[c]);
    if (l == 31) {
        #pragma unroll
        for (int c = 0; c < 8; ++c) P1[x0 + c + 1] = pk(0.f, v0A[c]);           // (v[-1],v[31])
    }
    if (l == 0) {
        #pragma unroll
        for (int c = 0; c < 8; ++c) P1[33 * PS + x0 + c + 1] = pk(v0B[c], 0.f); // (v[32],v[64])
    }

    // ---- packed weights -> registers (loop-invariant residents) ----
    ull ww[45];
    #pragma unroll
    for (int k = 0; k < 45; ++k) ww[k] = s_ww[k];
    __syncthreads();

    // ---- 79 Bellman iterations (even it: P1 -> P0) ----
    for (int it = 0; it < 79; ++it) {
        const ull* vi = (it & 1) ? P0 : P1;
        ull*       vo = (it & 1) ? P1 : P0;
        ull acc[5][8];
        bellman(acc, vi, qrs, ww, l, x0, t);

        float mA[8], mB[8];
        #pragma unroll
        for (int c = 0; c < 8; ++c) {
            float2 m = up(acc[0][c]);
            #pragma unroll
            for (int a = 1; a < 5; ++a) {
                float2 q = up(acc[a][c]);
                m.x = fmaxf(m.x, q.x);
                m.y = fmaxf(m.y, q.y);
            }
            mA[c] = m.x; mB[c] = m.y;
            vo[(l + 1) * PS + x0 + c + 1] = pk(m.x, m.y);
        }
        if (l == 31) {
            #pragma unroll
            for (int c = 0; c < 8; ++c) vo[x0 + c + 1] = pk(0.f, mA[c]);
        }
        if (l == 0) {
            #pragma unroll
            for (int c = 0; c < 8; ++c) vo[33 * PS + x0 + c + 1] = pk(mB[c], 0.f);
        }
        __syncthreads();
    }

    // ---- final q from P0 ----
    ull acc[5][8];
    bellman(acc, P0, qrs, ww, l, x0, t);

    const int sx = coords[b * 4 + 0];
    const int sy = coords[b * 4 + 1];
    float* oq = out_q + (size_t)b * 5 * NPIX;

    #pragma unroll
    for (int a = 0; a < 5; ++a) {
        float2 f[8];
        #pragma unroll
        for (int c = 0; c < 8; ++c) f[c] = up(acc[a][c]);
        float* baseA = oq + a * NPIX + l * 64 + x0;
        float* baseB = oq + a * NPIX + (l + 32) * 64 + x0;
        *reinterpret_cast<float4*>(baseA)     = make_float4(f[0].x, f[1].x, f[2].x, f[3].x);
        *reinterpret_cast<float4*>(baseA + 4) = make_float4(f[4].x, f[5].x, f[6].x, f[7].x);
        *reinterpret_cast<float4*>(baseB)     = make_float4(f[0].y, f[1].y, f[2].y, f[3].y);
        *reinterpret_cast<float4*>(baseB + 4) = make_float4(f[4].y, f[5].y, f[6].y, f[7].y);
        if (sy >= x0 && sy < x0 + 8) {
            if (sx == l)      out_logits[b * 5 + a] = f[sy - x0].x;
            if (sx == l + 32) out_logits[b * 5 + a] = f[sy - x0].y;
        }
    }
}

extern "C" void kernel_launch(void* const* d_in, const int* in_sizes, int n_in,
                              void* d_out, int out_size) {
    const float* input  = (const float*)d_in[0];
    const int*   coords = (const int*)  d_in[1];
    const float* w_h    = (const float*)d_in[2];
    const float* b_h    = (const float*)d_in[3];
    const float* w_r    = (const float*)d_in[4];
    const float* w_q    = (const float*)d_in[5];
    const float* w_w    = (const float*)d_in[6];
    float* out = (float*)d_out;

    const int smem_bytes = (2 * PPLANE + 40 * 256) * sizeof(ull);
    cudaFuncSetAttribute(vin_kernel, cudaFuncAttributeMaxDynamicSharedMemorySize, smem_bytes);
    vin_kernel<<<128, 256, smem_bytes>>>(input, coords, w_h, b_h, w_r, w_q, w_w,
                                         out, out + 128 * 5 * NPIX);
}